// round 1
// baseline (speedup 1.0000x reference)
#include <cuda_runtime.h>
#include <math.h>

#define Bc   8
#define Tc   2048
#define Ec   64
#define Hc   8
#define DKc  8
#define FFc  256
#define NTOK (Bc*Tc)

// Scratch (device globals: no allocations allowed)
__device__ float g_q[Bc*Hc*Tc*DKc];     // [b,h,t,d]  4MB
__device__ float g_k[Bc*Hc*Tc*DKc];
__device__ float g_v[Bc*Hc*Tc*DKc];
__device__ float g_attn[NTOK*Ec];       // [b,t,h,d] == [n, e]
__device__ float g_x1[NTOK*Ec];

// ---------------------------------------------------------------------------
// K1: q/k/v = cos(x @ W^T + b + theta_attn), written in [b,h,t,d] layout
// ---------------------------------------------------------------------------
__global__ __launch_bounds__(128) void qkv_kernel(
    const float* __restrict__ x,
    const float* __restrict__ Wq, const float* __restrict__ bq,
    const float* __restrict__ Wk, const float* __restrict__ bk,
    const float* __restrict__ Wv, const float* __restrict__ bv,
    const float* __restrict__ theta_p)
{
    extern __shared__ float sm[];
    float* sWq = sm;
    float* sWk = sm + 4096;
    float* sWv = sm + 8192;
    float* sb  = sm + 12288;   // bq[64] bk[64] bv[64]
    int tid = threadIdx.x;
    for (int i = tid; i < 4096; i += 128) { sWq[i] = Wq[i]; sWk[i] = Wk[i]; sWv[i] = Wv[i]; }
    if (tid < 64) { sb[tid] = bq[tid]; sb[64+tid] = bk[tid]; sb[128+tid] = bv[tid]; }
    __syncthreads();

    float theta = theta_p[0];
    int n = blockIdx.x * 128 + tid;

    float xr[64];
    const float4* x4 = reinterpret_cast<const float4*>(x + (size_t)n * Ec);
#pragma unroll
    for (int i = 0; i < 16; i++) {
        float4 v = x4[i];
        xr[4*i+0] = v.x; xr[4*i+1] = v.y; xr[4*i+2] = v.z; xr[4*i+3] = v.w;
    }
    int b = n >> 11, t = n & 2047;
    int base = b * (Hc*Tc*DKc) + t * DKc;

    for (int h = 0; h < Hc; h++) {
        float q8[8], k8[8], v8[8];
#pragma unroll
        for (int d = 0; d < 8; d++) {
            int o = h*8 + d;
            const float* wq = sWq + o*64;
            const float* wk = sWk + o*64;
            const float* wv = sWv + o*64;
            float a0=0.f,a1=0.f,a2=0.f,a3=0.f;
            float c0=0.f,c1=0.f,c2=0.f,c3=0.f;
            float e0=0.f,e1=0.f,e2=0.f,e3=0.f;
#pragma unroll
            for (int i = 0; i < 64; i += 4) {
                a0 = fmaf(xr[i+0], wq[i+0], a0); a1 = fmaf(xr[i+1], wq[i+1], a1);
                a2 = fmaf(xr[i+2], wq[i+2], a2); a3 = fmaf(xr[i+3], wq[i+3], a3);
                c0 = fmaf(xr[i+0], wk[i+0], c0); c1 = fmaf(xr[i+1], wk[i+1], c1);
                c2 = fmaf(xr[i+2], wk[i+2], c2); c3 = fmaf(xr[i+3], wk[i+3], c3);
                e0 = fmaf(xr[i+0], wv[i+0], e0); e1 = fmaf(xr[i+1], wv[i+1], e1);
                e2 = fmaf(xr[i+2], wv[i+2], e2); e3 = fmaf(xr[i+3], wv[i+3], e3);
            }
            q8[d] = cosf((a0+a1) + (a2+a3) + sb[o]       + theta);
            k8[d] = cosf((c0+c1) + (c2+c3) + sb[64+o]    + theta);
            v8[d] = cosf((e0+e1) + (e2+e3) + sb[128+o]   + theta);
        }
        int off = base + h * (Tc*DKc);
        *reinterpret_cast<float4*>(g_q + off)     = make_float4(q8[0],q8[1],q8[2],q8[3]);
        *reinterpret_cast<float4*>(g_q + off + 4) = make_float4(q8[4],q8[5],q8[6],q8[7]);
        *reinterpret_cast<float4*>(g_k + off)     = make_float4(k8[0],k8[1],k8[2],k8[3]);
        *reinterpret_cast<float4*>(g_k + off + 4) = make_float4(k8[4],k8[5],k8[6],k8[7]);
        *reinterpret_cast<float4*>(g_v + off)     = make_float4(v8[0],v8[1],v8[2],v8[3]);
        *reinterpret_cast<float4*>(g_v + off + 4) = make_float4(v8[4],v8[5],v8[6],v8[7]);
    }
}

// ---------------------------------------------------------------------------
// K2: attention. One block per (b,h, q-tile of 256 rows); K,V tiles in SMEM.
// Scores bounded (|s|<=2.83) -> single-pass softmax without max subtraction.
// log2e folded into pre-scaled q so exp is a bare ex2.approx.
// ---------------------------------------------------------------------------
__global__ __launch_bounds__(256) void attn_kernel()
{
    extern __shared__ float sm[];
    float4* K4 = reinterpret_cast<float4*>(sm);
    float4* V4 = reinterpret_cast<float4*>(sm + Tc*DKc);

    int bh  = blockIdx.x;   // 0..63
    int qt  = blockIdx.y;   // 0..7
    int tid = threadIdx.x;

    const float4* gk4 = reinterpret_cast<const float4*>(g_k + (size_t)bh * (Tc*DKc));
    const float4* gv4 = reinterpret_cast<const float4*>(g_v + (size_t)bh * (Tc*DKc));
#pragma unroll
    for (int i = 0; i < 16; i++) {
        K4[tid + 256*i] = gk4[tid + 256*i];
        V4[tid + 256*i] = gv4[tid + 256*i];
    }
    __syncthreads();

    int t = qt * 256 + tid;
    const float* qp = g_q + (size_t)bh * (Tc*DKc) + t * DKc;
    const float QS = 0.35355339059327f * 1.4426950408889634f;  // 1/sqrt(8) * log2(e)
    float q0=qp[0]*QS, q1=qp[1]*QS, q2=qp[2]*QS, q3=qp[3]*QS;
    float q4=qp[4]*QS, q5=qp[5]*QS, q6=qp[6]*QS, q7=qp[7]*QS;

    float l  = 0.f;
    float a0=0.f,a1=0.f,a2=0.f,a3=0.f,a4=0.f,a5=0.f,a6=0.f,a7=0.f;

    const float4* kp = K4;
    const float4* vp = V4;
#pragma unroll 4
    for (int j = 0; j < Tc; j++) {
        float4 ka = kp[0], kb = kp[1]; kp += 2;
        float s = fmaf(q0, ka.x, fmaf(q1, ka.y, fmaf(q2, ka.z, q3*ka.w)))
                + fmaf(q4, kb.x, fmaf(q5, kb.y, fmaf(q6, kb.z, q7*kb.w)));
        float p;
        asm("ex2.approx.f32 %0, %1;" : "=f"(p) : "f"(s));
        float4 va = vp[0], vb = vp[1]; vp += 2;
        l += p;
        a0 = fmaf(p, va.x, a0); a1 = fmaf(p, va.y, a1);
        a2 = fmaf(p, va.z, a2); a3 = fmaf(p, va.w, a3);
        a4 = fmaf(p, vb.x, a4); a5 = fmaf(p, vb.y, a5);
        a6 = fmaf(p, vb.z, a6); a7 = fmaf(p, vb.w, a7);
    }
    float inv = 1.0f / l;

    int b = bh >> 3, h = bh & 7;
    float* op = g_attn + ((size_t)(b*Tc + t)) * Ec + h * DKc;
    reinterpret_cast<float4*>(op)[0] = make_float4(a0*inv, a1*inv, a2*inv, a3*inv);
    reinterpret_cast<float4*>(op)[1] = make_float4(a4*inv, a5*inv, a6*inv, a7*inv);
}

// ---------------------------------------------------------------------------
// K3: x1 = LN(x + attn @ Wo^T + bo, g1, be1)
// ---------------------------------------------------------------------------
__global__ __launch_bounds__(128) void oproj_kernel(
    const float* __restrict__ x, const float* __restrict__ Wo,
    const float* __restrict__ bo, const float* __restrict__ g1,
    const float* __restrict__ be1)
{
    extern __shared__ float sm[];
    float* sWo = sm;            // 4096
    float* sbo = sm + 4096;
    float* sg  = sm + 4160;
    float* sbe = sm + 4224;
    int tid = threadIdx.x;
    for (int i = tid; i < 4096; i += 128) sWo[i] = Wo[i];
    if (tid < 64) { sbo[tid] = bo[tid]; sg[tid] = g1[tid]; sbe[tid] = be1[tid]; }
    __syncthreads();

    int n = blockIdx.x * 128 + tid;

    float a[64];
    const float4* a4 = reinterpret_cast<const float4*>(g_attn + (size_t)n * Ec);
#pragma unroll
    for (int i = 0; i < 16; i++) {
        float4 v = a4[i];
        a[4*i+0] = v.x; a[4*i+1] = v.y; a[4*i+2] = v.z; a[4*i+3] = v.w;
    }
    float r[64];
    const float4* x4 = reinterpret_cast<const float4*>(x + (size_t)n * Ec);
#pragma unroll
    for (int i = 0; i < 16; i++) {
        float4 v = x4[i];
        r[4*i+0] = v.x; r[4*i+1] = v.y; r[4*i+2] = v.z; r[4*i+3] = v.w;
    }

    float s1 = 0.f;
    for (int e = 0; e < 64; e++) {
        const float* w = sWo + e*64;
        float c0=0.f,c1=0.f,c2=0.f,c3=0.f;
#pragma unroll
        for (int i = 0; i < 64; i += 4) {
            c0 = fmaf(a[i+0], w[i+0], c0); c1 = fmaf(a[i+1], w[i+1], c1);
            c2 = fmaf(a[i+2], w[i+2], c2); c3 = fmaf(a[i+3], w[i+3], c3);
        }
        float rv = r[e] + (c0+c1) + (c2+c3) + sbo[e];
        r[e] = rv;
        s1 += rv;
    }
    float m  = s1 * (1.f/64.f);
    float s2 = 0.f;
    for (int e = 0; e < 64; e++) { float d = r[e] - m; s2 = fmaf(d, d, s2); }
    float rs = rsqrtf(s2 * (1.f/64.f) + 1e-5f);

    float* o = g_x1 + (size_t)n * Ec;
    for (int e = 0; e < 64; e++) o[e] = (r[e] - m) * rs * sg[e] + sbe[e];
}

// ---------------------------------------------------------------------------
// K4: out = LN(x1 + relu(cos(x1)*cos(theta_ffn) @ W1^T + b1) @ W2^T + b2, g2, be2)
// ---------------------------------------------------------------------------
__global__ __launch_bounds__(128) void ffn_kernel(
    const float* __restrict__ W1, const float* __restrict__ b1,
    const float* __restrict__ W2, const float* __restrict__ b2,
    const float* __restrict__ g2, const float* __restrict__ be2,
    const float* __restrict__ theta_p, float* __restrict__ out)
{
    extern __shared__ float sm[];
    float* sW1  = sm;            // [256][64]  16384
    float* sW2t = sm + 16384;    // [256][64]  transposed W2
    float* sb1  = sm + 32768;    // 256
    float* sb2  = sm + 33024;    // 64
    float* sg   = sm + 33088;    // 64
    float* sbe  = sm + 33152;    // 64
    int tid = threadIdx.x;
    for (int i = tid; i < 16384; i += 128) sW1[i] = W1[i];
    for (int i = tid; i < 16384; i += 128) {           // smem-linear, conflict-free stores
        int f = i >> 6, e = i & 63;
        sW2t[i] = W2[e * FFc + f];
    }
    for (int i = tid; i < 256; i += 128) sb1[i] = b1[i];
    if (tid < 64) { sb2[tid] = b2[tid]; sg[tid] = g2[tid]; sbe[tid] = be2[tid]; }
    __syncthreads();

    float ct = cosf(theta_p[0]);
    int n = blockIdx.x * 128 + tid;

    float qc[64], y[64];
    const float4* x14 = reinterpret_cast<const float4*>(g_x1 + (size_t)n * Ec);
#pragma unroll
    for (int i = 0; i < 16; i++) {
        float4 v = x14[i];
        y[4*i+0] = v.x + sb2[4*i+0];  qc[4*i+0] = cosf(v.x) * ct;
        y[4*i+1] = v.y + sb2[4*i+1];  qc[4*i+1] = cosf(v.y) * ct;
        y[4*i+2] = v.z + sb2[4*i+2];  qc[4*i+2] = cosf(v.z) * ct;
        y[4*i+3] = v.w + sb2[4*i+3];  qc[4*i+3] = cosf(v.w) * ct;
    }

    for (int f = 0; f < FFc; f++) {
        const float* w = sW1 + f*64;
        float h0=0.f,h1=0.f,h2=0.f,h3=0.f;
#pragma unroll
        for (int i = 0; i < 64; i += 4) {
            h0 = fmaf(qc[i+0], w[i+0], h0); h1 = fmaf(qc[i+1], w[i+1], h1);
            h2 = fmaf(qc[i+2], w[i+2], h2); h3 = fmaf(qc[i+3], w[i+3], h3);
        }
        float hf = (h0+h1) + (h2+h3) + sb1[f];
        hf = fmaxf(hf, 0.f);
        const float* w2 = sW2t + f*64;
#pragma unroll
        for (int e = 0; e < 64; e++) y[e] = fmaf(hf, w2[e], y[e]);
    }

    float s1 = 0.f;
#pragma unroll
    for (int e = 0; e < 64; e++) s1 += y[e];
    float m  = s1 * (1.f/64.f);
    float s2 = 0.f;
#pragma unroll
    for (int e = 0; e < 64; e++) { float d = y[e] - m; s2 = fmaf(d, d, s2); }
    float rs = rsqrtf(s2 * (1.f/64.f) + 1e-5f);

    float* op = out + (size_t)n * Ec;
#pragma unroll
    for (int i = 0; i < 16; i++) {
        float4 v;
        v.x = (y[4*i+0] - m) * rs * sg[4*i+0] + sbe[4*i+0];
        v.y = (y[4*i+1] - m) * rs * sg[4*i+1] + sbe[4*i+1];
        v.z = (y[4*i+2] - m) * rs * sg[4*i+2] + sbe[4*i+2];
        v.w = (y[4*i+3] - m) * rs * sg[4*i+3] + sbe[4*i+3];
        reinterpret_cast<float4*>(op)[i] = v;
    }
}

// ---------------------------------------------------------------------------
extern "C" void kernel_launch(void* const* d_in, const int* in_sizes, int n_in,
                              void* d_out, int out_size)
{
    const float* x     = (const float*)d_in[0];
    const float* Wq    = (const float*)d_in[1];
    const float* bq    = (const float*)d_in[2];
    const float* Wk    = (const float*)d_in[3];
    const float* bk    = (const float*)d_in[4];
    const float* Wv    = (const float*)d_in[5];
    const float* bv    = (const float*)d_in[6];
    const float* Wo    = (const float*)d_in[7];
    const float* bo    = (const float*)d_in[8];
    const float* th_a  = (const float*)d_in[9];
    const float* th_f  = (const float*)d_in[10];
    const float* W1    = (const float*)d_in[11];
    const float* b1    = (const float*)d_in[12];
    const float* W2    = (const float*)d_in[13];
    const float* b2    = (const float*)d_in[14];
    const float* g1    = (const float*)d_in[15];
    const float* be1   = (const float*)d_in[16];
    const float* g2    = (const float*)d_in[17];
    const float* be2   = (const float*)d_in[18];
    float* out = (float*)d_out;

    const size_t SM1 = (3*4096 + 192) * sizeof(float);          // 49,920 B
    const size_t SM2 = (size_t)2 * Tc * DKc * sizeof(float);    // 131,072 B
    const size_t SM3 = (4096 + 192) * sizeof(float);            // 17,152 B
    const size_t SM4 = (2*16384 + 256 + 192) * sizeof(float);   // 132,864 B

    cudaFuncSetAttribute(qkv_kernel,  cudaFuncAttributeMaxDynamicSharedMemorySize, (int)SM1);
    cudaFuncSetAttribute(attn_kernel, cudaFuncAttributeMaxDynamicSharedMemorySize, (int)SM2);
    cudaFuncSetAttribute(ffn_kernel,  cudaFuncAttributeMaxDynamicSharedMemorySize, (int)SM4);

    qkv_kernel<<<NTOK/128, 128, SM1>>>(x, Wq, bq, Wk, bk, Wv, bv, th_a);
    attn_kernel<<<dim3(Bc*Hc, Tc/256), 256, SM2>>>();
    oproj_kernel<<<NTOK/128, 128, SM3>>>(x, Wo, bo, g1, be1);
    ffn_kernel<<<NTOK/128, 128, SM4>>>(W1, b1, W2, b2, g2, be2, th_f, out);
}